// round 4
// baseline (speedup 1.0000x reference)
#include <cuda_runtime.h>

// PureCartesianTensorProductO3Sparse — R4: 2 CTAs/SM, gmem-direct x reads,
// compact conflict-free weights via per-lane rotated chunk addressing.
//
// Warp shape: 8 olanes x 4 row-slots. Thread computes o1=olane, o2=olane+8
// for one row, reading x operands directly from gmem (L1).
// Weights in smem, PLAIN layout [p][a][o][16] (96 KB, no padding).
// Conflict-free trick: lane olane loads physical 16B chunk ((pj + rot)&3),
// rot=(olane>>1)&3, so the 8 lanes of an LDS.128 tile all 32 banks.
// The thread's t[] registers therefore hold a chunk-rotated view of b;
// every stage-2 operand address uses runtime chunk base lc[pj] to match.

constexpr int ROW_IN  = 416;
constexpr int WELEMS  = 6 * 16 * 16 * 16;   // 24576 floats = 96 KB
constexpr int THREADS = 256;                 // 8 warps per CTA
constexpr int SLOTS   = THREADS / 8;         // 32 rows in flight per CTA

__global__ __launch_bounds__(THREADS, 2)
void tp_o3_kernel(const float* __restrict__ x1,
                  const float* __restrict__ x2,
                  const float* __restrict__ wgt,
                  float* __restrict__ out,
                  int N)
{
    extern __shared__ float ws[];   // [p][a][o][16] = 24576 floats

    const int tid = threadIdx.x;

    // gmem [p][o][a][b] -> smem [p][a][o][b]
    for (int idx = tid; idx < WELEMS; idx += THREADS) {
        int p = idx >> 12;
        int o = (idx >> 8) & 15;
        int a = (idx >> 4) & 15;
        int b = idx & 15;
        ws[(p << 12) + (a << 8) + (o << 4) + b] = wgt[idx];
    }
    __syncthreads();

    const int olane = tid & 7;
    const int slot  = tid >> 3;
    const int o1 = olane, o2 = olane + 8;
    const int rot = (olane >> 1) & 3;

    // logical-b chunk base held in physical register chunk pj (floats)
    const int lc0 = (((0 + rot) & 3) << 2);
    const int lc1 = (((1 + rot) & 3) << 2);
    const int lc2 = (((2 + rot) & 3) << 2);
    const int lc3 = (((3 + rot) & 3) << 2);

    // weight base pointers (chunk-rotated) per path for both o's
    const float* wb1 = ws + (o1 << 4);
    const float* wb2 = ws + (o2 << 4);

    const int rstride = (int)gridDim.x * SLOTS;

    for (int row = (int)blockIdx.x * SLOTS + slot; row < N; row += rstride) {
        const float* xa = x1 + (size_t)row * ROW_IN;
        const float* xb = x2 + (size_t)row * ROW_IN;

        float acc0_1 = 0.f, acc0_2 = 0.f;
        float acc1_1[3] = {0.f,0.f,0.f}, acc1_2[3] = {0.f,0.f,0.f};
        float acc2_1[9] = {0.f,0.f,0.f,0.f,0.f,0.f,0.f,0.f,0.f};
        float acc2_2[9] = {0.f,0.f,0.f,0.f,0.f,0.f,0.f,0.f,0.f};

        float A0[16];
        {
            const float4* av = reinterpret_cast<const float4*>(xa);
            #pragma unroll
            for (int j = 0; j < 4; j++) {
                float4 q = av[j];
                A0[4*j] = q.x; A0[4*j+1] = q.y; A0[4*j+2] = q.z; A0[4*j+3] = q.w;
            }
        }

        // B0 in rotated (physical) order — matches t[] layout
        float B0r[16];
        {
            float4 q;
            q = *reinterpret_cast<const float4*>(xb + lc0);
            B0r[0] = q.x;  B0r[1] = q.y;  B0r[2] = q.z;  B0r[3] = q.w;
            q = *reinterpret_cast<const float4*>(xb + lc1);
            B0r[4] = q.x;  B0r[5] = q.y;  B0r[6] = q.z;  B0r[7] = q.w;
            q = *reinterpret_cast<const float4*>(xb + lc2);
            B0r[8] = q.x;  B0r[9] = q.y;  B0r[10] = q.z; B0r[11] = q.w;
            q = *reinterpret_cast<const float4*>(xb + lc3);
            B0r[12] = q.x; B0r[13] = q.y; B0r[14] = q.z; B0r[15] = q.w;
        }

        float t1[16], t2[16];

        // t{1,2}[pj*4+b'] = sum_a A0[a] * W[p][a][o{1,2}][lc(pj)+b']
        auto stage1 = [&](int p) {
            #pragma unroll
            for (int i = 0; i < 16; i++) { t1[i] = 0.f; t2[i] = 0.f; }
            const float* w1 = wb1 + (p << 12);
            const float* w2 = wb2 + (p << 12);
            #pragma unroll
            for (int a = 0; a < 16; a++) {
                float av = A0[a];
                const float* wa1 = w1 + (a << 8);
                const float* wa2 = w2 + (a << 8);
                float4 q;
                q = *reinterpret_cast<const float4*>(wa1 + lc0);
                t1[0] =fmaf(av,q.x,t1[0]);  t1[1] =fmaf(av,q.y,t1[1]);
                t1[2] =fmaf(av,q.z,t1[2]);  t1[3] =fmaf(av,q.w,t1[3]);
                q = *reinterpret_cast<const float4*>(wa1 + lc1);
                t1[4] =fmaf(av,q.x,t1[4]);  t1[5] =fmaf(av,q.y,t1[5]);
                t1[6] =fmaf(av,q.z,t1[6]);  t1[7] =fmaf(av,q.w,t1[7]);
                q = *reinterpret_cast<const float4*>(wa1 + lc2);
                t1[8] =fmaf(av,q.x,t1[8]);  t1[9] =fmaf(av,q.y,t1[9]);
                t1[10]=fmaf(av,q.z,t1[10]); t1[11]=fmaf(av,q.w,t1[11]);
                q = *reinterpret_cast<const float4*>(wa1 + lc3);
                t1[12]=fmaf(av,q.x,t1[12]); t1[13]=fmaf(av,q.y,t1[13]);
                t1[14]=fmaf(av,q.z,t1[14]); t1[15]=fmaf(av,q.w,t1[15]);
                q = *reinterpret_cast<const float4*>(wa2 + lc0);
                t2[0] =fmaf(av,q.x,t2[0]);  t2[1] =fmaf(av,q.y,t2[1]);
                t2[2] =fmaf(av,q.z,t2[2]);  t2[3] =fmaf(av,q.w,t2[3]);
                q = *reinterpret_cast<const float4*>(wa2 + lc1);
                t2[4] =fmaf(av,q.x,t2[4]);  t2[5] =fmaf(av,q.y,t2[5]);
                t2[6] =fmaf(av,q.z,t2[6]);  t2[7] =fmaf(av,q.w,t2[7]);
                q = *reinterpret_cast<const float4*>(wa2 + lc2);
                t2[8] =fmaf(av,q.x,t2[8]);  t2[9] =fmaf(av,q.y,t2[9]);
                t2[10]=fmaf(av,q.z,t2[10]); t2[11]=fmaf(av,q.w,t2[11]);
                q = *reinterpret_cast<const float4*>(wa2 + lc3);
                t2[12]=fmaf(av,q.x,t2[12]); t2[13]=fmaf(av,q.y,t2[13]);
                t2[14]=fmaf(av,q.z,t2[14]); t2[15]=fmaf(av,q.w,t2[15]);
            }
        };

        // ---- path 0 (0,0)
        stage1(0);
        {
            float u1a=0.f,u1b=0.f,u2a=0.f,u2b=0.f;
            #pragma unroll
            for (int i = 0; i < 16; i += 2) {
                u1a = fmaf(t1[i],   B0r[i],   u1a);
                u1b = fmaf(t1[i+1], B0r[i+1], u1b);
                u2a = fmaf(t2[i],   B0r[i],   u2a);
                u2b = fmaf(t2[i+1], B0r[i+1], u2b);
            }
            acc0_1 = u1a + u1b;
            acc0_2 = u2a + u2b;
        }

        // ---- path 1 (0,1): operands at logical b = lc[pj]+b'
        stage1(1);
        {
            const int lcs[4] = {lc0, lc1, lc2, lc3};
            #pragma unroll
            for (int pj = 0; pj < 4; pj++) {
                const float* e = xb + 16 + 3 * lcs[pj];
                #pragma unroll
                for (int bp = 0; bp < 4; bp++) {
                    float tb1 = t1[pj*4 + bp], tb2 = t2[pj*4 + bp];
                    float e0 = e[3*bp + 0], e1 = e[3*bp + 1], e2 = e[3*bp + 2];
                    acc1_1[0] = fmaf(tb1, e0, acc1_1[0]);
                    acc1_1[1] = fmaf(tb1, e1, acc1_1[1]);
                    acc1_1[2] = fmaf(tb1, e2, acc1_1[2]);
                    acc1_2[0] = fmaf(tb2, e0, acc1_2[0]);
                    acc1_2[1] = fmaf(tb2, e1, acc1_2[1]);
                    acc1_2[2] = fmaf(tb2, e2, acc1_2[2]);
                }
            }
        }

        // ---- path 2 (0,2)
        stage1(2);
        {
            const int lcs[4] = {lc0, lc1, lc2, lc3};
            #pragma unroll
            for (int pj = 0; pj < 4; pj++) {
                const float* e = xb + 64 + 9 * lcs[pj];
                #pragma unroll
                for (int bp = 0; bp < 4; bp++) {
                    float tb1 = t1[pj*4 + bp], tb2 = t2[pj*4 + bp];
                    #pragma unroll
                    for (int k = 0; k < 9; k++) {
                        float ev = e[9*bp + k];
                        acc2_1[k] = fmaf(tb1, ev, acc2_1[k]);
                        acc2_2[k] = fmaf(tb2, ev, acc2_2[k]);
                    }
                }
            }
        }

        // dot of a rotated weight row with B0r (rotation-consistent)
        auto dotB0 = [&](const float* wa) -> float {
            float4 q0 = *reinterpret_cast<const float4*>(wa + lc0);
            float4 q1 = *reinterpret_cast<const float4*>(wa + lc1);
            float4 q2 = *reinterpret_cast<const float4*>(wa + lc2);
            float4 q3 = *reinterpret_cast<const float4*>(wa + lc3);
            float u0 = B0r[0]*q0.x, u1 = B0r[4]*q1.x, u2 = B0r[8]*q2.x, u3 = B0r[12]*q3.x;
            u0 = fmaf(B0r[1], q0.y,u0); u0 = fmaf(B0r[2], q0.z,u0); u0 = fmaf(B0r[3], q0.w,u0);
            u1 = fmaf(B0r[5], q1.y,u1); u1 = fmaf(B0r[6], q1.z,u1); u1 = fmaf(B0r[7], q1.w,u1);
            u2 = fmaf(B0r[9], q2.y,u2); u2 = fmaf(B0r[10],q2.z,u2); u2 = fmaf(B0r[11],q2.w,u2);
            u3 = fmaf(B0r[13],q3.y,u3); u3 = fmaf(B0r[14],q3.z,u3); u3 = fmaf(B0r[15],q3.w,u3);
            return (u0 + u1) + (u2 + u3);
        };

        // ---- path 3 (1,0)
        {
            const float* w1 = wb1 + (3 << 12);
            const float* w2 = wb2 + (3 << 12);
            #pragma unroll
            for (int a = 0; a < 16; a++) {
                float s1 = dotB0(w1 + (a << 8));
                float s2 = dotB0(w2 + (a << 8));
                float e0 = xa[16 + 3*a + 0];
                float e1 = xa[16 + 3*a + 1];
                float e2 = xa[16 + 3*a + 2];
                acc1_1[0] = fmaf(s1, e0, acc1_1[0]);
                acc1_1[1] = fmaf(s1, e1, acc1_1[1]);
                acc1_1[2] = fmaf(s1, e2, acc1_1[2]);
                acc1_2[0] = fmaf(s2, e0, acc1_2[0]);
                acc1_2[1] = fmaf(s2, e1, acc1_2[1]);
                acc1_2[2] = fmaf(s2, e2, acc1_2[2]);
            }
        }

        // ---- path 5 (2,0)
        {
            const float* w1 = wb1 + (5 << 12);
            const float* w2 = wb2 + (5 << 12);
            #pragma unroll
            for (int a = 0; a < 16; a++) {
                float s1 = dotB0(w1 + (a << 8));
                float s2 = dotB0(w2 + (a << 8));
                #pragma unroll
                for (int k = 0; k < 9; k++) {
                    float ev = xa[64 + 9*a + k];
                    acc2_1[k] = fmaf(s1, ev, acc2_1[k]);
                    acc2_2[k] = fmaf(s2, ev, acc2_2[k]);
                }
            }
        }

        // ---- path 4 (1,1): B1t in rotated order; v computed per (a, o)
        {
            float B1t[3][16];
            {
                const int lcs[4] = {lc0, lc1, lc2, lc3};
                #pragma unroll
                for (int pj = 0; pj < 4; pj++) {
                    const float* e = xb + 16 + 3 * lcs[pj];
                    #pragma unroll
                    for (int bp = 0; bp < 4; bp++) {
                        B1t[0][pj*4+bp] = e[3*bp + 0];
                        B1t[1][pj*4+bp] = e[3*bp + 1];
                        B1t[2][pj*4+bp] = e[3*bp + 2];
                    }
                }
            }
            const float* w1 = wb1 + (4 << 12);
            const float* w2 = wb2 + (4 << 12);
            #pragma unroll
            for (int a = 0; a < 16; a++) {
                float w[16];
                float v10,v11,v12, v20,v21,v22;
                {
                    const float* wa = w1 + (a << 8);
                    float4 q0 = *reinterpret_cast<const float4*>(wa + lc0);
                    float4 q1 = *reinterpret_cast<const float4*>(wa + lc1);
                    float4 q2 = *reinterpret_cast<const float4*>(wa + lc2);
                    float4 q3 = *reinterpret_cast<const float4*>(wa + lc3);
                    w[0]=q0.x;w[1]=q0.y;w[2]=q0.z;w[3]=q0.w;
                    w[4]=q1.x;w[5]=q1.y;w[6]=q1.z;w[7]=q1.w;
                    w[8]=q2.x;w[9]=q2.y;w[10]=q2.z;w[11]=q2.w;
                    w[12]=q3.x;w[13]=q3.y;w[14]=q3.z;w[15]=q3.w;
                    float a0=0.f,b0=0.f,a1=0.f,b1=0.f,a2=0.f,b2=0.f;
                    #pragma unroll
                    for (int i = 0; i < 16; i += 2) {
                        a0 = fmaf(w[i],   B1t[0][i],   a0);
                        b0 = fmaf(w[i+1], B1t[0][i+1], b0);
                        a1 = fmaf(w[i],   B1t[1][i],   a1);
                        b1 = fmaf(w[i+1], B1t[1][i+1], b1);
                        a2 = fmaf(w[i],   B1t[2][i],   a2);
                        b2 = fmaf(w[i+1], B1t[2][i+1], b2);
                    }
                    v10 = a0+b0; v11 = a1+b1; v12 = a2+b2;
                }
                {
                    const float* wa = w2 + (a << 8);
                    float4 q0 = *reinterpret_cast<const float4*>(wa + lc0);
                    float4 q1 = *reinterpret_cast<const float4*>(wa + lc1);
                    float4 q2 = *reinterpret_cast<const float4*>(wa + lc2);
                    float4 q3 = *reinterpret_cast<const float4*>(wa + lc3);
                    w[0]=q0.x;w[1]=q0.y;w[2]=q0.z;w[3]=q0.w;
                    w[4]=q1.x;w[5]=q1.y;w[6]=q1.z;w[7]=q1.w;
                    w[8]=q2.x;w[9]=q2.y;w[10]=q2.z;w[11]=q2.w;
                    w[12]=q3.x;w[13]=q3.y;w[14]=q3.z;w[15]=q3.w;
                    float a0=0.f,b0=0.f,a1=0.f,b1=0.f,a2=0.f,b2=0.f;
                    #pragma unroll
                    for (int i = 0; i < 16; i += 2) {
                        a0 = fmaf(w[i],   B1t[0][i],   a0);
                        b0 = fmaf(w[i+1], B1t[0][i+1], b0);
                        a1 = fmaf(w[i],   B1t[1][i],   a1);
                        b1 = fmaf(w[i+1], B1t[1][i+1], b1);
                        a2 = fmaf(w[i],   B1t[2][i],   a2);
                        b2 = fmaf(w[i+1], B1t[2][i+1], b2);
                    }
                    v20 = a0+b0; v21 = a1+b1; v22 = a2+b2;
                }
                float a10 = xa[16 + 3*a + 0];
                float a11 = xa[16 + 3*a + 1];
                float a12 = xa[16 + 3*a + 2];
                acc2_1[0]=fmaf(a10,v10,acc2_1[0]); acc2_1[1]=fmaf(a10,v11,acc2_1[1]); acc2_1[2]=fmaf(a10,v12,acc2_1[2]);
                acc2_1[3]=fmaf(a11,v10,acc2_1[3]); acc2_1[4]=fmaf(a11,v11,acc2_1[4]); acc2_1[5]=fmaf(a11,v12,acc2_1[5]);
                acc2_1[6]=fmaf(a12,v10,acc2_1[6]); acc2_1[7]=fmaf(a12,v11,acc2_1[7]); acc2_1[8]=fmaf(a12,v12,acc2_1[8]);
                acc2_2[0]=fmaf(a10,v20,acc2_2[0]); acc2_2[1]=fmaf(a10,v21,acc2_2[1]); acc2_2[2]=fmaf(a10,v22,acc2_2[2]);
                acc2_2[3]=fmaf(a11,v20,acc2_2[3]); acc2_2[4]=fmaf(a11,v21,acc2_2[4]); acc2_2[5]=fmaf(a11,v22,acc2_2[5]);
                acc2_2[6]=fmaf(a12,v20,acc2_2[6]); acc2_2[7]=fmaf(a12,v21,acc2_2[7]); acc2_2[8]=fmaf(a12,v22,acc2_2[8]);
            }
        }

        // ---- write results + zero upper half
        float* orow = out + (size_t)row * ROW_IN;
        orow[o1] = acc0_1;
        orow[o2] = acc0_2;
        #pragma unroll
        for (int i = 0; i < 3; i++) {
            orow[16 + 3*o1 + i] = acc1_1[i];
            orow[16 + 3*o2 + i] = acc1_2[i];
        }
        #pragma unroll
        for (int k = 0; k < 9; k++) {
            orow[64 + 9*o1 + k] = acc2_1[k];
            orow[64 + 9*o2 + k] = acc2_2[k];
        }
        {
            float4 z = make_float4(0.f, 0.f, 0.f, 0.f);
            float4* oz = reinterpret_cast<float4*>(orow + 208);
            #pragma unroll
            for (int j = 0; j < 7; j++) {
                int c = olane + 8*j;
                if (c < 52) oz[c] = z;
            }
        }
    }
}

extern "C" void kernel_launch(void* const* d_in, const int* in_sizes, int n_in,
                              void* d_out, int out_size)
{
    const float* x1 = (const float*)d_in[0];
    const float* x2 = (const float*)d_in[1];
    const float* w  = (const float*)d_in[2];
    float* out = (float*)d_out;
    const int N = in_sizes[0] / ROW_IN;

    const int smem_bytes = WELEMS * (int)sizeof(float);  // 98304

    int smcount = 0;
    cudaDeviceGetAttribute(&smcount, cudaDevAttrMultiProcessorCount, 0);
    if (smcount <= 0) smcount = 148;
    cudaFuncSetAttribute(tp_o3_kernel, cudaFuncAttributeMaxDynamicSharedMemorySize,
                         smem_bytes);

    tp_o3_kernel<<<2 * smcount, THREADS, smem_bytes>>>(x1, x2, w, out, N);
}